// round 8
// baseline (speedup 1.0000x reference)
#include <cuda_runtime.h>

#define NN 400
#define FF 240
#define CC 32
#define LL 1440
#define NK 304
#define SIN_X2 480   // row index of swE in sw; swEt at 481

// ---- scratch (device globals; no allocation allowed) ----
__device__ float g_XiT[CC * NN];   // transposed: [c][node]
__device__ float g_XjT[CC * NN];
__device__ float g_aggI0[NN * CC];
__device__ float g_aggI1[NN * CC];
__device__ float g_aggJ0[NN * CC];
__device__ float g_aggJ1[NN * CC];
__device__ float g_e1[NN * NN];
__device__ float g_e1T[NN * NN];
__device__ float g_aT[NN * NN];
__device__ float g_eT[NN * NN];
__device__ float g_x1[NN * FF];
__device__ float g_x2[NN * FF];

// ============================================================
// K1: fused launch. blocks [0,100): xw layer1 (XiT/XjT from input x)
//                  blocks [100,185): transpose tiles (a->aT, e->eT)
// ============================================================
__global__ void __launch_bounds__(1024) prep_xw_kernel(
    const float* __restrict__ x, const float* __restrict__ sw,
    const float* __restrict__ sb,
    const float* __restrict__ a, const float* __restrict__ e)
{
    __shared__ __align__(16) float sx[4][FF];
    __shared__ float part[4][8][CC];
    __shared__ float tbuf[4][32][33];
    int tid = threadIdx.x;

    if (blockIdx.x < 100) {
        int row0 = blockIdx.x * 4;
        for (int idx = tid; idx < 4 * FF; idx += 1024)
            sx[idx / FF][idx % FF] = x[row0 * FF + idx];
        __syncthreads();

        int kq = tid >> 8;
        int t2 = tid & 255;
        int w = t2 >> 5, c = t2 & 31;
        int r = w & 3;
        bool isJ = (w >= 4);
        const float* wb = sw + (isJ ? FF * CC : 0) + c + kq * 60 * CC;
        float a0 = 0.f, a1 = 0.f, a2 = 0.f, a3 = 0.f;
        const float4* sxr = (const float4*)sx[r] + kq * 15;
#pragma unroll
        for (int f4 = 0; f4 < 15; f4++) {
            float4 xv = sxr[f4];
            int f = f4 * 4;
            a0 += xv.x * __ldg(wb + (f + 0) * CC);
            a1 += xv.y * __ldg(wb + (f + 1) * CC);
            a2 += xv.z * __ldg(wb + (f + 2) * CC);
            a3 += xv.w * __ldg(wb + (f + 3) * CC);
        }
        part[kq][w][c] = (a0 + a1) + (a2 + a3);
        __syncthreads();
        if (kq == 0) {
            float v = (part[0][w][c] + part[1][w][c]) + (part[2][w][c] + part[3][w][c]);
            if (!isJ) v += sb[c];
            (isJ ? g_XjT : g_XiT)[c * NN + row0 + r] = v;
        }
    } else {
        int sub = tid >> 8;
        int t2 = tid & 255;
        int tile = (blockIdx.x - 100) * 4 + sub;
        int tx = t2 & 31, ty = t2 >> 5;
        bool valid = (tile < 338);
        const float* src = nullptr;
        float* dst = nullptr;
        int x0 = 0, y0 = 0;
        if (valid) {
            bool isE = (tile >= 169);
            int tIdx = isE ? tile - 169 : tile;
            src = isE ? e : a;
            dst = isE ? g_eT : g_aT;
            x0 = (tIdx % 13) * 32;
            y0 = (tIdx / 13) * 32;
#pragma unroll
            for (int r = 0; r < 32; r += 8) {
                int y = y0 + ty + r, xx = x0 + tx;
                if (y < NN && xx < NN) tbuf[sub][ty + r][tx] = src[y * NN + xx];
            }
        }
        __syncthreads();
        if (valid) {
#pragma unroll
            for (int r = 0; r < 32; r += 8) {
                int y = x0 + ty + r, xx = y0 + tx;
                if (y < NN && xx < NN) dst[y * NN + xx] = tbuf[sub][tx][ty + r];
            }
        }
    }
}

// ============================================================
// K2: per-pair kernel. Grid 1600:
//   b = mode*800 + fixed*2 + vhalf
// Block = 128 thr, 1 fixed node, 200 v-values.
//   vg = tid>>2 owns node v (stride 32); qt = tid&3 owns channels
//   [qt*8, qt*8+8) with the per-channel q tuple held in REGISTERS
//   (no LDS in hot loop). 2 shuffles finish the gate/edge dots.
// Partial aggregates -> per-vhalf buffers (summed in node kernel).
// ============================================================
template <int LAYER>
__global__ void __launch_bounds__(128) pair_kernel(
    const float* __restrict__ eParam, const float* __restrict__ a,
    const float* __restrict__ sw,
    const float* __restrict__ aiw, const float* __restrict__ aib,
    const float* __restrict__ ajw, const float* __restrict__ ajb,
    const float* __restrict__ ew,  const float* __restrict__ eb)
{
    __shared__ float sRed[32][36];

    const float* e  = (LAYER == 2) ? g_e1  : eParam;
    const float* eT = (LAYER == 2) ? g_e1T : g_eT;
    int b = blockIdx.x;
    bool colMode = (b >= 800);
    int bb = colMode ? b - 800 : b;
    int fixed = bb >> 1;
    int vhalf = bb & 1;

    int tid = threadIdx.x;
    int vg = tid >> 2;
    int qt = tid & 3;

    const float* xTf = colMode ? g_XjT : g_XiT;   // fixed-node table
    const float* xTv = colMode ? g_XiT : g_XjT;   // varying-node table
    const float* pA   = (colMode ? eT : e)  + fixed * NN;
    const float* pB   = (colMode ? e  : eT) + fixed * NN;
    const float* pAdj = (colMode ? g_aT : a) + fixed * NN;
    float gb  = colMode ? ajb[0] : aib[0];
    float ebv = (LAYER == 1) ? eb[0] : 0.f;
    float* eOut = (colMode ? g_e1T : g_e1) + fixed * NN;

    // per-channel loop-invariant tuple in registers
    float qx[8], qy[8], qz[8], qw[8], qe[8];
#pragma unroll
    for (int k = 0; k < 8; k++) {
        int c = qt * 8 + k;
        qx[k] = __ldg(xTf + c * NN + fixed);
        qy[k] = __ldg(sw + SIN_X2 * CC + c);
        qz[k] = __ldg(sw + (SIN_X2 + 1) * CC + c);
        qw[k] = colMode ? __ldg(ajw + c) : __ldg(aiw + c);
        if (LAYER == 1) qe[k] = __ldg(ew + c);
    }
    const float* xv = xTv + (qt * 8) * NN;

    float acc[8];
#pragma unroll
    for (int k = 0; k < 8; k++) acc[k] = 0.f;

    int vend = vhalf * 200 + 200;
    for (int v = vhalf * 200 + vg; v < vend; v += 32) {
        float eij = __ldg(pA + v);
        float eji = __ldg(pB + v);
        float av  = __ldg(pAdj + v);

        float s = 0.f, se = 0.f;
        float tv[8];
#pragma unroll
        for (int k = 0; k < 8; k++) {
            float vvv = __ldg(xv + k * NN + v);
            float t = qx[k] + vvv + eij * qy[k] + eji * qz[k];
            t = fmaxf(t, 0.f) * av;
            tv[k] = t;
            s += t * qw[k];
            if (LAYER == 1) se += t * qe[k];
        }
        s += __shfl_xor_sync(0xffffffffu, s, 1);
        s += __shfl_xor_sync(0xffffffffu, s, 2);
        if (LAYER == 1) {
            se += __shfl_xor_sync(0xffffffffu, se, 1);
            se += __shfl_xor_sync(0xffffffffu, se, 2);
        }
        float gate = 1.f / (1.f + __expf(-(s + gb)));
#pragma unroll
        for (int k = 0; k < 8; k++) acc[k] += gate * tv[k];
        if (LAYER == 1 && qt == 0) eOut[v] = se + ebv;
    }

    // block reduce over the 32 v-groups
    {
        float* dstr = &sRed[vg][qt * 8];
        *(float4*)(dstr)     = *(float4*)(acc);
        *(float4*)(dstr + 4) = *(float4*)(acc + 4);
    }
    __syncthreads();
    if (tid < CC) {
        float p = 0.f;
#pragma unroll 8
        for (int r = 0; r < 32; r++) p += sRed[r][tid];
        float* dst = colMode ? (vhalf ? g_aggJ1 : g_aggJ0)
                             : (vhalf ? g_aggI1 : g_aggI0);
        dst[fixed * CC + tid] = p;
    }
}

// ============================================================
// K3: node model  x_out = [x, aggI, aggJ] @ nw + nb  (K=304)
// 1024 thr: kq = tid>>7 (8 K-slices of 38), cg = tid&127
// (120 active colgroups x 2 cols; coalesced LDG.64 weights,
// broadcast LDS activations). 4 rows/block, grid 100.
// LAYER 1 additionally computes XiT/XjT for layer 2 (fused xw2).
// ============================================================
template <int LAYER>
__global__ void __launch_bounds__(1024) node_kernel(
    const float* __restrict__ xin, const float* __restrict__ nw,
    const float* __restrict__ nb,
    const float* __restrict__ sw2, const float* __restrict__ sb2)
{
    const float* x = (LAYER == 1) ? xin : g_x1;
    float* xout = (LAYER == 1) ? g_x1 : g_x2;
    __shared__ float s[4][NK];
    __shared__ float part[8][4][FF];
    __shared__ float sx1[4][FF];
    int row0 = blockIdx.x * 4;
    int tid = threadIdx.x;
    for (int idx = tid; idx < 4 * NK; idx += 1024) {
        int r = idx / NK, k = idx % NK;
        float v;
        if (k < FF)            v = x[(row0 + r) * FF + k];
        else if (k < FF + CC)  v = g_aggI0[(row0 + r) * CC + (k - FF)]
                                 + g_aggI1[(row0 + r) * CC + (k - FF)];
        else                   v = g_aggJ0[(row0 + r) * CC + (k - FF - CC)]
                                 + g_aggJ1[(row0 + r) * CC + (k - FF - CC)];
        s[r][k] = v;
    }
    __syncthreads();

    int kq = tid >> 7;
    int cg = tid & 127;
    if (cg < 120) {
        int f0 = cg * 2;
        const float* wp = nw + f0;
        float2 a0 = {0.f, 0.f}, a1 = {0.f, 0.f}, a2 = {0.f, 0.f}, a3 = {0.f, 0.f};
#pragma unroll 2
        for (int kk = 0; kk < 38; kk++) {
            int k = kq * 38 + kk;
            float2 w = *(const float2*)(wp + k * FF);
            float x0 = s[0][k], x1 = s[1][k], x2 = s[2][k], x3 = s[3][k];
            a0.x += x0 * w.x; a0.y += x0 * w.y;
            a1.x += x1 * w.x; a1.y += x1 * w.y;
            a2.x += x2 * w.x; a2.y += x2 * w.y;
            a3.x += x3 * w.x; a3.y += x3 * w.y;
        }
        *(float2*)&part[kq][0][f0] = a0;
        *(float2*)&part[kq][1][f0] = a1;
        *(float2*)&part[kq][2][f0] = a2;
        *(float2*)&part[kq][3][f0] = a3;
    }
    __syncthreads();
    for (int idx = tid; idx < 4 * FF; idx += 1024) {
        int r = idx / FF, f2 = idx % FF;
        float v = ((part[0][r][f2] + part[1][r][f2]) + (part[2][r][f2] + part[3][r][f2]))
                + ((part[4][r][f2] + part[5][r][f2]) + (part[6][r][f2] + part[7][r][f2]))
                + nb[f2];
        xout[(row0 + r) * FF + f2] = v;
        if (LAYER == 1) sx1[r][f2] = v;
    }

    if (LAYER == 1) {
        // fused xw for layer 2: XiT/XjT = (x1 @ sw2)^T (+ sb2 for Xi)
        __syncthreads();
        int kq4 = tid >> 8;
        int t2 = tid & 255;
        int r = t2 >> 6, c = t2 & 63;
        const float* wq = sw2 + ((c < 32) ? 0 : FF * CC) + (c & 31);
        float acc = 0.f;
#pragma unroll 4
        for (int k = 0; k < 60; k++) {
            int kk = kq4 * 60 + k;
            acc += sx1[r][kk] * __ldg(wq + kk * CC);
        }
        part[kq4][r][c] = acc;
        __syncthreads();
        if (kq4 == 0) {
            float v = (part[0][r][c] + part[1][r][c]) +
                      (part[2][r][c] + part[3][r][c]);
            if (c < 32) g_XiT[c * NN + row0 + r] = v + sb2[c];
            else        g_XjT[(c - 32) * NN + row0 + r] = v;
        }
    }
}

// ============================================================
// K4: out = x2 @ dw + db   (400 x 1440, K=240)
// ============================================================
__global__ void __launch_bounds__(256) out_kernel(
    const float* __restrict__ dw, const float* __restrict__ db,
    float* __restrict__ out)
{
    __shared__ float s[8][FF];
    __shared__ float part[3][8][240];
    int tid = threadIdx.x;
    int row0 = blockIdx.y * 8;
    int colbase = blockIdx.x * 240;
    for (int idx = tid; idx < 8 * FF; idx += 256)
        s[idx / FF][idx % FF] = g_x2[row0 * FF + idx];
    __syncthreads();

    int kq = tid >> 6, cg = tid & 63;
    float4 acc[8];
#pragma unroll
    for (int r = 0; r < 8; r++) acc[r] = make_float4(0.f, 0.f, 0.f, 0.f);

    if (cg < 60) {
        const float* wp = dw + colbase + cg * 4;
        int kbase = kq * 60;
#pragma unroll 4
        for (int kk = 0; kk < 60; kk++) {
            int k = kbase + kk;
            float4 w = *(const float4*)(wp + k * LL);
#pragma unroll
            for (int r = 0; r < 8; r++) {
                float xr = s[r][k];
                acc[r].x += xr * w.x;
                acc[r].y += xr * w.y;
                acc[r].z += xr * w.z;
                acc[r].w += xr * w.w;
            }
        }
        if (kq > 0) {
#pragma unroll
            for (int r = 0; r < 8; r++)
                *(float4*)&part[kq - 1][r][cg * 4] = acc[r];
        }
    }
    __syncthreads();
    if (kq == 0 && cg < 60) {
        float4 bv = *(const float4*)(db + colbase + cg * 4);
#pragma unroll
        for (int r = 0; r < 8; r++) {
            float4 p0 = *(const float4*)&part[0][r][cg * 4];
            float4 p1 = *(const float4*)&part[1][r][cg * 4];
            float4 p2 = *(const float4*)&part[2][r][cg * 4];
            float4 v;
            v.x = acc[r].x + p0.x + p1.x + p2.x + bv.x;
            v.y = acc[r].y + p0.y + p1.y + p2.y + bv.y;
            v.z = acc[r].z + p0.z + p1.z + p2.z + bv.z;
            v.w = acc[r].w + p0.w + p1.w + p2.w + bv.w;
            *(float4*)(out + (row0 + r) * LL + colbase + cg * 4) = v;
        }
    }
}

// ============================================================
extern "C" void kernel_launch(void* const* d_in, const int* in_sizes, int n_in,
                              void* d_out, int out_size)
{
    const float* x      = (const float*)d_in[0];
    const float* a      = (const float*)d_in[1];
    const float* e      = (const float*)d_in[2];
    const float* c1_sw  = (const float*)d_in[3];
    const float* c1_sb  = (const float*)d_in[4];
    const float* c1_aiw = (const float*)d_in[5];
    const float* c1_aib = (const float*)d_in[6];
    const float* c1_ajw = (const float*)d_in[7];
    const float* c1_ajb = (const float*)d_in[8];
    const float* c1_nw  = (const float*)d_in[9];
    const float* c1_nb  = (const float*)d_in[10];
    const float* c1_ew  = (const float*)d_in[11];
    const float* c1_eb  = (const float*)d_in[12];
    const float* c2_sw  = (const float*)d_in[13];
    const float* c2_sb  = (const float*)d_in[14];
    const float* c2_aiw = (const float*)d_in[15];
    const float* c2_aib = (const float*)d_in[16];
    const float* c2_ajw = (const float*)d_in[17];
    const float* c2_ajb = (const float*)d_in[18];
    const float* c2_nw  = (const float*)d_in[19];
    const float* c2_nb  = (const float*)d_in[20];
    const float* c2_ew  = (const float*)d_in[21];
    const float* c2_eb  = (const float*)d_in[22];
    const float* dw     = (const float*)d_in[23];
    const float* db     = (const float*)d_in[24];
    float* out = (float*)d_out;

    // ---- layer 1 (xw + transposes fused in one launch) ----
    prep_xw_kernel<<<185, 1024>>>(x, c1_sw, c1_sb, a, e);
    pair_kernel<1><<<1600, 128>>>(e, a, c1_sw, c1_aiw, c1_aib, c1_ajw, c1_ajb,
                                  c1_ew, c1_eb);
    node_kernel<1><<<NN / 4, 1024>>>(x, c1_nw, c1_nb, c2_sw, c2_sb);

    // ---- layer 2 (XiT/XjT already produced by node_kernel<1>) ----
    pair_kernel<2><<<1600, 128>>>(nullptr, a, c2_sw, c2_aiw, c2_aib, c2_ajw, c2_ajb,
                                  c2_ew, c2_eb);
    node_kernel<2><<<NN / 4, 1024>>>(nullptr, c2_nw, c2_nb, nullptr, nullptr);

    // ---- readout ----
    out_kernel<<<dim3(6, NN / 8), 256>>>(dw, db, out);
}